// round 14
// baseline (speedup 1.0000x reference)
#include <cuda_runtime.h>
#include <cuda_bf16.h>
#include <cuda_fp16.h>
#include <math.h>
#include <stdint.h>

#define Bq 2
#define Tq 1024
#define Dq 2048
#define Hq 8
#define DKq 128
#define DVq 256
#define KDq 1024
#define VDq 2048
#define Mrows (Bq*Tq)   // 2048
#define GK 2048         // K for every big GEMM
#define NFUSE 6144      // q(1024) + k(1024) + v(2048) + gate(2048)

// ------------------------- scratch (device globals) -------------------------
__device__ float g_proj[Mrows*NFUSE];        // fused projection output
__device__ float g_qc[Mrows*KDq];
__device__ float g_kc[Mrows*KDq];
__device__ float g_vc[Mrows*VDq];
__device__ float g_gd[Mrows*Hq];
__device__ float g_bt[Mrows*Hq];
__device__ float g_orow[Mrows*VDq];

// fp16 split (hi/lo) operands; B side hi-only
__device__ __half g_hh[Mrows*Dq],    g_hl[Mrows*Dq];
__device__ __half g_wh[NFUSE*Dq];
__device__ __half g_owh[Dq*VDq];
__device__ __half g_onh[Mrows*VDq],  g_onl[Mrows*VDq];

// ------------------------- helpers ------------------------------------------
__device__ __forceinline__ uint32_t smem_u32(const void* p) {
    uint32_t a;
    asm("{ .reg .u64 t; cvta.to.shared.u64 t, %1; cvt.u32.u64 %0, t; }" : "=r"(a) : "l"(p));
    return a;
}
__device__ __forceinline__ void cp16(uint32_t dst, const void* src) {
    asm volatile("cp.async.cg.shared.global [%0], [%1], 16;" :: "r"(dst), "l"(src));
}
__device__ __forceinline__ void cp4(uint32_t dst, const void* src) {
    asm volatile("cp.async.ca.shared.global [%0], [%1], 4;" :: "r"(dst), "l"(src));
}
__device__ __forceinline__ void cp_commit() {
    asm volatile("cp.async.commit_group;" ::: "memory");
}
template <int N>
__device__ __forceinline__ void cp_wait() {
    asm volatile("cp.async.wait_group %0;" :: "n"(N) : "memory");
}
__device__ __forceinline__ void ldsm_x4(uint32_t addr, uint32_t* r) {
    asm volatile("ldmatrix.sync.aligned.m8n8.x4.shared.b16 {%0,%1,%2,%3}, [%4];"
                 : "=r"(r[0]), "=r"(r[1]), "=r"(r[2]), "=r"(r[3]) : "r"(addr));
}
__device__ __forceinline__ void mma_f16(float* c, const uint32_t* a, const uint32_t* b) {
    asm volatile(
        "mma.sync.aligned.m16n8k16.row.col.f32.f16.f16.f32 "
        "{%0,%1,%2,%3}, {%4,%5,%6,%7}, {%8,%9}, {%0,%1,%2,%3};"
        : "+f"(c[0]), "+f"(c[1]), "+f"(c[2]), "+f"(c[3])
        : "r"(a[0]), "r"(a[1]), "r"(a[2]), "r"(a[3]), "r"(b[0]), "r"(b[1]));
}

// ------------------------- split fp16 HMMA GEMM (2-pass, 2 CTA/SM) ----------
// C = A*B^T, A as fp16 hi/lo pair, B as fp16 hi only.
// A*B ~= Ah*Bh + Al*Bh (dropped A*Bl term ~2^-12 relative, within 1e-3 gate).
#define ROWB 80
#define MATB (128*ROWB)              // 10240 B per matrix
#define STGB (3*MATB)                // Ah,Al,Bh per stage = 30720 B
#define SMEM_GEMM (2*STGB)           // 61440 B

__global__ void __launch_bounds__(256, 2) hgemm_nt_split(
    const __half* __restrict__ Ah, const __half* __restrict__ Al,
    const __half* __restrict__ Bh,
    float* __restrict__ C, int N)
{
    extern __shared__ char smem[];
    const uint32_t sb = smem_u32(smem);
    const int tid = threadIdx.x, wid = tid >> 5, lane = tid & 31;
    const int bm = blockIdx.y * 128, bn = blockIdx.x * 128;
    const int wm = (wid >> 1) * 32;
    const int wn = (wid & 1) * 64;

    float acc[2][8][4];
#pragma unroll
    for (int i = 0; i < 2; i++)
#pragma unroll
        for (int j = 0; j < 8; j++)
#pragma unroll
            for (int l = 0; l < 4; l++) acc[i][j][l] = 0.f;

    const int NC = GK / 32;

#define PREFETCH(cc, ss)                                                          \
    {                                                                             \
        const int kc = (cc) * 32;                                                 \
        const uint32_t stg = sb + (uint32_t)(ss) * STGB;                          \
        _Pragma("unroll")                                                         \
        for (int i = 0; i < 2; i++) {                                             \
            int idx = tid + i * 256;                                              \
            int row = idx >> 2, seg = idx & 3;                                    \
            uint32_t so = (uint32_t)(row * ROWB + seg * 16);                      \
            size_t ea = (size_t)(bm + row) * GK + kc + seg * 8;                   \
            size_t eb = (size_t)(bn + row) * GK + kc + seg * 8;                   \
            cp16(stg + so,            Ah + ea);                                   \
            cp16(stg + MATB + so,     Al + ea);                                   \
            cp16(stg + 2*MATB + so,   Bh + eb);                                   \
        }                                                                         \
        cp_commit();                                                              \
    }

    PREFETCH(0, 0);
    PREFETCH(1, 1);

    const uint32_t a_row = (uint32_t)(wm + (lane & 15));
    const uint32_t a_colb = (uint32_t)((lane >> 4) * 16);
    const uint32_t b_row0 = (uint32_t)(wn + (lane & 7) + ((lane >> 4) << 3));
    const uint32_t b_colb = (uint32_t)(((lane >> 3) & 1) * 16);

    for (int c = 0; c < NC; c++) {
        if (c == NC - 1) cp_wait<0>(); else cp_wait<1>();
        __syncthreads();
        const uint32_t stg = sb + (uint32_t)(c & 1) * STGB;

#pragma unroll
        for (int k16 = 0; k16 < 2; k16++) {
            const uint32_t kb = (uint32_t)(k16 * 32);
            uint32_t a0[2][4], a1[2][4], bb[4][4];

            // pass 1: Ah*Bh (16 distinct accs)
#pragma unroll
            for (int mt = 0; mt < 2; mt++) {
                uint32_t ao = (a_row + mt * 16) * ROWB + kb + a_colb;
                ldsm_x4(stg + ao, a0[mt]);
            }
#pragma unroll
            for (int np = 0; np < 4; np++) {
                uint32_t bo = (b_row0 + np * 16) * ROWB + kb + b_colb;
                ldsm_x4(stg + 2*MATB + bo, bb[np]);
            }
#pragma unroll
            for (int mt = 0; mt < 2; mt++)
#pragma unroll
                for (int np = 0; np < 4; np++) {
                    mma_f16(acc[mt][np*2],   a0[mt], bb[np]);
                    mma_f16(acc[mt][np*2+1], a0[mt], bb[np] + 2);
                }

            // pass 2: Al*Bh (16 distinct accs)
#pragma unroll
            for (int mt = 0; mt < 2; mt++) {
                uint32_t ao = (a_row + mt * 16) * ROWB + kb + a_colb;
                ldsm_x4(stg + MATB + ao, a1[mt]);
            }
#pragma unroll
            for (int mt = 0; mt < 2; mt++)
#pragma unroll
                for (int np = 0; np < 4; np++) {
                    mma_f16(acc[mt][np*2],   a1[mt], bb[np]);
                    mma_f16(acc[mt][np*2+1], a1[mt], bb[np] + 2);
                }
        }
        __syncthreads();
        if (c + 2 < NC) PREFETCH(c + 2, c & 1);
    }
#undef PREFETCH

#pragma unroll
    for (int mt = 0; mt < 2; mt++) {
        int r0 = bm + wm + mt * 16 + (lane >> 2);
#pragma unroll
        for (int nt = 0; nt < 8; nt++) {
            int col = bn + wn + nt * 8 + (lane & 3) * 2;
            float2 v0 = make_float2(acc[mt][nt][0], acc[mt][nt][1]);
            float2 v1 = make_float2(acc[mt][nt][2], acc[mt][nt][3]);
            *(float2*)(C + (size_t)r0 * N + col)       = v0;
            *(float2*)(C + (size_t)(r0 + 8) * N + col) = v1;
        }
    }
}

// ------------------------- fp32 -> fp16 hi/lo split -------------------------
__device__ __forceinline__ void split4h(float4 v, __half* hi, __half* lo) {
    __half hx = __float2half(v.x), hy = __float2half(v.y);
    __half hz = __float2half(v.z), hw = __float2half(v.w);
    __half2 h0, h1, l0, l1;
    h0.x = hx; h0.y = hy; h1.x = hz; h1.y = hw;
    l0.x = __float2half(v.x - __half2float(hx));
    l0.y = __float2half(v.y - __half2float(hy));
    l1.x = __float2half(v.z - __half2float(hz));
    l1.y = __float2half(v.w - __half2float(hw));
    *(__half2*)(hi)     = h0;
    *(__half2*)(hi + 2) = h1;
    *(__half2*)(lo)     = l0;
    *(__half2*)(lo + 2) = l1;
}
__device__ __forceinline__ void cvt4h(float4 v, __half* hi) {
    __half2 h0, h1;
    h0.x = __float2half(v.x); h0.y = __float2half(v.y);
    h1.x = __float2half(v.z); h1.y = __float2half(v.w);
    *(__half2*)(hi)     = h0;
    *(__half2*)(hi + 2) = h1;
}

__global__ void cvt_split(const float* __restrict__ x,
                          __half* __restrict__ hi,
                          __half* __restrict__ lo, int n)
{
    int i = (blockIdx.x * blockDim.x + threadIdx.x) * 4;
    if (i >= n) return;
    split4h(*(const float4*)(x + i), hi + i, lo + i);
}

// fused weight convert (hi only): rows 0-1023 q_w, 1024-2047 k_w, 2048-4095 v_w, 4096-6143 g_w
__global__ void cvt_w4(const float* __restrict__ qw, const float* __restrict__ kw,
                       const float* __restrict__ vw, const float* __restrict__ gw,
                       __half* __restrict__ hi)
{
    int i = (blockIdx.x * blockDim.x + threadIdx.x) * 4;
    int row = i >> 11;
    int col = i & 2047;
    const float* src;
    if (row < 1024)      src = qw + (size_t)row * Dq + col;
    else if (row < 2048) src = kw + (size_t)(row - 1024) * Dq + col;
    else if (row < 4096) src = vw + (size_t)(row - 2048) * Dq + col;
    else                 src = gw + (size_t)(row - 4096) * Dq + col;
    cvt4h(*(const float4*)src, hi + i);
}

__global__ void cvt_h(const float* __restrict__ x, __half* __restrict__ hi, int n)
{
    int i = (blockIdx.x * blockDim.x + threadIdx.x) * 4;
    if (i >= n) return;
    cvt4h(*(const float4*)(x + i), hi + i);
}

// ------------------------- a/b projections -> decay g and beta --------------
__device__ __forceinline__ float softplus_f(float x) {
    return fmaxf(x, 0.f) + log1pf(expf(-fabsf(x)));
}

__global__ void proj_ab_kernel(const float* __restrict__ h,
                               const float* __restrict__ a_w,
                               const float* __restrict__ b_w,
                               const float* __restrict__ A_log,
                               const float* __restrict__ dt_bias,
                               float* __restrict__ gd, float* __restrict__ bt)
{
    int w = (blockIdx.x * blockDim.x + threadIdx.x) >> 5;
    int lane = threadIdx.x & 31;
    if (w >= Mrows) return;
    const float* hr = h + (size_t)w * Dq;
    float acc[16];
#pragma unroll
    for (int p = 0; p < 16; p++) acc[p] = 0.f;
    for (int j = lane * 4; j < Dq; j += 128) {
        float4 hv = *(const float4*)(hr + j);
#pragma unroll
        for (int p = 0; p < 8; p++) {
            float4 av = *(const float4*)(a_w + (size_t)p * Dq + j);
            acc[p] += hv.x * av.x + hv.y * av.y + hv.z * av.z + hv.w * av.w;
            float4 bv = *(const float4*)(b_w + (size_t)p * Dq + j);
            acc[8 + p] += hv.x * bv.x + hv.y * bv.y + hv.z * bv.z + hv.w * bv.w;
        }
    }
#pragma unroll
    for (int p = 0; p < 16; p++)
#pragma unroll
        for (int m = 16; m; m >>= 1)
            acc[p] += __shfl_xor_sync(0xffffffffu, acc[p], m);

    if (lane < 8) {
        float x = acc[lane] + dt_bias[lane];
        gd[w * Hq + lane] = -expf(A_log[lane]) * softplus_f(x);
    } else if (lane < 16) {
        int p = lane - 8;
        bt[w * Hq + p] = 1.f / (1.f + expf(-acc[lane]));
    }
}

// ---------------- fused conv+SiLU+l2norm for q/k (head dim 128) -------------
__global__ void conv_l2_kernel(const float* __restrict__ P, int colofs,
                               const float* __restrict__ w, float* __restrict__ out)
{
    int gwp = (blockIdx.x * blockDim.x + threadIdx.x) >> 5;
    int lane = threadIdx.x & 31;
    int row = gwp >> 3, hh = gwp & 7;
    int t = row & (Tq - 1);
    int c = hh * 128 + lane * 4;
    const float* base = P + (size_t)row * NFUSE + colofs + c;
    float4 x0 = *(const float4*)base;
    float4 x1 = make_float4(0,0,0,0), x2 = x1, x3 = x1;
    if (t >= 1) x1 = *(const float4*)(base - NFUSE);
    if (t >= 2) x2 = *(const float4*)(base - 2*NFUSE);
    if (t >= 3) x3 = *(const float4*)(base - 3*NFUSE);
    float4 wc0 = *(const float4*)(w + (size_t)(c + 0) * 4);
    float4 wc1 = *(const float4*)(w + (size_t)(c + 1) * 4);
    float4 wc2 = *(const float4*)(w + (size_t)(c + 2) * 4);
    float4 wc3 = *(const float4*)(w + (size_t)(c + 3) * 4);
    float v0 = x0.x*wc0.w + x1.x*wc0.z + x2.x*wc0.y + x3.x*wc0.x;
    float v1 = x0.y*wc1.w + x1.y*wc1.z + x2.y*wc1.y + x3.y*wc1.x;
    float v2 = x0.z*wc2.w + x1.z*wc2.z + x2.z*wc2.y + x3.z*wc2.x;
    float v3 = x0.w*wc3.w + x1.w*wc3.z + x2.w*wc3.y + x3.w*wc3.x;
    v0 = v0 / (1.f + expf(-v0));
    v1 = v1 / (1.f + expf(-v1));
    v2 = v2 / (1.f + expf(-v2));
    v3 = v3 / (1.f + expf(-v3));
    float ss = v0*v0 + v1*v1 + v2*v2 + v3*v3;
#pragma unroll
    for (int m = 16; m; m >>= 1) ss += __shfl_xor_sync(0xffffffffu, ss, m);
    float r = rsqrtf(ss + 1e-6f);
    *(float4*)(out + (size_t)row * KDq + c) =
        make_float4(v0 * r, v1 * r, v2 * r, v3 * r);
}

// ---------------- conv+SiLU for v (elementwise, strided read) ---------------
__global__ void conv_silu_stride(const float* __restrict__ P, int colofs,
                                 const float* __restrict__ w, float* __restrict__ out)
{
    int i = blockIdx.x * blockDim.x + threadIdx.x;
    int c = i % VDq;
    int row = i / VDq;
    int t = row & (Tq - 1);
    const float* base = P + (size_t)row * NFUSE + colofs + c;
    float4 wc = *(const float4*)(w + (size_t)c * 4);
    float acc = base[0] * wc.w;
    if (t >= 1) acc += base[-1 * NFUSE] * wc.z;
    if (t >= 2) acc += base[-2 * NFUSE] * wc.y;
    if (t >= 3) acc += base[-3 * NFUSE] * wc.x;
    out[i] = acc / (1.f + expf(-acc));
}

// ------------------------- gated delta-rule scan (16-col chunks) ------------
#define TS 16
#define GSTR 160
#define QOFF (TS*GSTR)
#define VOFF (2*TS*GSTR)
#define GOFF (VOFF + TS*16)
#define SSZ  (GOFF + 32)

__global__ void __launch_bounds__(128) scan_kernel(const float* __restrict__ q,
                                                   const float* __restrict__ k,
                                                   const float* __restrict__ v,
                                                   const float* __restrict__ gdec,
                                                   const float* __restrict__ beta,
                                                   float* __restrict__ o)
{
    const int vchunk = blockIdx.x;
    const int h = blockIdx.y;
    const int b = blockIdx.z;
    const int tid = threadIdx.x;
    const int col = tid >> 3;
    const int rgrp = tid & 7;
    const int c0 = vchunk * 16;

    __shared__ float sbuf[2 * SSZ];
    const uint32_t sb = smem_u32(sbuf);

    float S[16];
#pragma unroll
    for (int i = 0; i < 16; i++) S[i] = 0.f;
    const float scale = 0.08838834764831843f;
    const int NT = Tq / TS;

#define SPRE(tt, ss)                                                              \
    {                                                                             \
        const int tb = (tt) * TS;                                                 \
        const uint32_t stb = sb + (uint32_t)(ss) * (SSZ * 4);                     \
        _Pragma("unroll")                                                         \
        for (int j = 0; j < 4; j++) {                                             \
            int idx = tid + j * 128;                                              \
            int s = idx >> 5, f = idx & 31;                                       \
            size_t gofs = ((size_t)(b * Tq + tb + s)) * KDq + h * DKq + f * 4;    \
            uint32_t so = (uint32_t)((s * GSTR + (f >> 2) * 20 + (f & 3) * 4)*4); \
            cp16(stb + so, k + gofs);                                             \
            cp16(stb + QOFF * 4 + so, q + gofs);                                  \
        }                                                                         \
        if (tid < 64) {                                                           \
            int s = tid >> 2, f = tid & 3;                                        \
            size_t gofs = ((size_t)(b * Tq + tb + s)) * VDq + h * DVq + c0 + f*4; \
            cp16(stb + (VOFF + s * 16 + f * 4) * 4, v + gofs);                    \
        } else if (tid < 80) {                                                    \
            int s = tid - 64;                                                     \
            cp4(stb + (GOFF + s) * 4, gdec + (size_t)(b * Tq + tb + s) * Hq + h); \
        } else if (tid < 96) {                                                    \
            int s = tid - 80;                                                     \
            cp4(stb + (GOFF + 16 + s) * 4, beta + (size_t)(b * Tq + tb + s) * Hq + h); \
        }                                                                         \
        cp_commit();                                                              \
    }

    SPRE(0, 0);
    SPRE(1, 1);

    for (int t = 0; t < NT; t++) {
        if (t == NT - 1) cp_wait<0>(); else cp_wait<1>();
        __syncthreads();
        const float* st = sbuf + (t & 1) * SSZ;
        const float* ksb = st;
        const float* qsb = st + QOFF;
        const float* vsb = st + VOFF;
        const float* gsb = st + GOFF;
        const int trow = b * Tq + t * TS;

#pragma unroll
        for (int s = 0; s < TS; s++) {
            const float* kb = ksb + s * GSTR + rgrp * 20;
            const float* qb = qsb + s * GSTR + rgrp * 20;
            float4 k0 = *(const float4*)(kb);
            float4 k1 = *(const float4*)(kb + 4);
            float4 k2 = *(const float4*)(kb + 8);
            float4 k3 = *(const float4*)(kb + 12);
            float kva = k0.x*S[0] + k0.y*S[1] + k0.z*S[2] + k0.w*S[3];
            float kvb = k1.x*S[4] + k1.y*S[5] + k1.z*S[6] + k1.w*S[7];
            float kvc = k2.x*S[8] + k2.y*S[9] + k2.z*S[10] + k2.w*S[11];
            float kvd = k3.x*S[12] + k3.y*S[13] + k3.z*S[14] + k3.w*S[15];
            float kv = (kva + kvb) + (kvc + kvd);
            kv += __shfl_xor_sync(0xffffffffu, kv, 1);
            kv += __shfl_xor_sync(0xffffffffu, kv, 2);
            kv += __shfl_xor_sync(0xffffffffu, kv, 4);
            float eg = expf(gsb[s]);
            float u = (vsb[s * 16 + col] - kv * eg) * gsb[16 + s];
            float4 q0 = *(const float4*)(qb);
            float4 q1 = *(const float4*)(qb + 4);
            float4 q2 = *(const float4*)(qb + 8);
            float4 q3 = *(const float4*)(qb + 12);
            S[0]  = S[0]*eg  + k0.x*u;  S[1]  = S[1]*eg  + k0.y*u;
            S[2]  = S[2]*eg  + k0.z*u;  S[3]  = S[3]*eg  + k0.w*u;
            S[4]  = S[4]*eg  + k1.x*u;  S[5]  = S[5]*eg  + k1.y*u;
            S[6]  = S[6]*eg  + k1.z*u;  S[7]  = S[7]*eg  + k1.w*u;
            S[8]  = S[8]*eg  + k2.x*u;  S[9]  = S[9]*eg  + k2.y*u;
            S[10] = S[10]*eg + k2.z*u;  S[11] = S[11]*eg + k2.w*u;
            S[12] = S[12]*eg + k3.x*u;  S[13] = S[13]*eg + k3.y*u;
            S[14] = S[14]*eg + k3.z*u;  S[15] = S[15]*eg + k3.w*u;
            float oa = q0.x*S[0] + q0.y*S[1] + q0.z*S[2] + q0.w*S[3];
            float ob = q1.x*S[4] + q1.y*S[5] + q1.z*S[6] + q1.w*S[7];
            float oc = q2.x*S[8] + q2.y*S[9] + q2.z*S[10] + q2.w*S[11];
            float od = q3.x*S[12] + q3.y*S[13] + q3.z*S[14] + q3.w*S[15];
            float ot = (oa + ob) + (oc + od);
            ot += __shfl_xor_sync(0xffffffffu, ot, 1);
            ot += __shfl_xor_sync(0xffffffffu, ot, 2);
            ot += __shfl_xor_sync(0xffffffffu, ot, 4);
            if (rgrp == 0)
                o[(size_t)(trow + s) * VDq + h * DVq + c0 + col] = ot * scale;
        }
        __syncthreads();
        if (t + 2 < NT) SPRE(t + 2, t & 1);
    }
#undef SPRE
}

// ------------------------- gated RMSNorm -> fp16 hi/lo ----------------------
__global__ void rmsnorm_gate_kernel(const float* __restrict__ o,
                                    const float* __restrict__ P,   // gate at col 4096
                                    const float* __restrict__ nw,
                                    __half* __restrict__ oh,
                                    __half* __restrict__ ol)
{
    int w = (blockIdx.x * blockDim.x + threadIdx.x) >> 5;
    int lane = threadIdx.x & 31;
    int row = w >> 3, hh = w & 7;
    const float* orow = o + (size_t)w * DVq;
    float4 o0 = *(const float4*)(orow + lane * 4);
    float4 o1 = *(const float4*)(orow + 128 + lane * 4);
    float ss = o0.x * o0.x + o0.y * o0.y + o0.z * o0.z + o0.w * o0.w
             + o1.x * o1.x + o1.y * o1.y + o1.z * o1.z + o1.w * o1.w;
#pragma unroll
    for (int m = 16; m; m >>= 1) ss += __shfl_xor_sync(0xffffffffu, ss, m);
    float r = rsqrtf(ss * (1.f / 256.f) + 1e-5f);
    const float* grow = P + (size_t)row * NFUSE + 4096 + hh * DVq;
    float4 g0 = *(const float4*)(grow + lane * 4);
    float4 g1 = *(const float4*)(grow + 128 + lane * 4);
    float4 w0 = *(const float4*)(nw + lane * 4);
    float4 w1 = *(const float4*)(nw + 128 + lane * 4);
    float f[8];
    f[0] = o0.x * r * w0.x * (g0.x / (1.f + expf(-g0.x)));
    f[1] = o0.y * r * w0.y * (g0.y / (1.f + expf(-g0.y)));
    f[2] = o0.z * r * w0.z * (g0.z / (1.f + expf(-g0.z)));
    f[3] = o0.w * r * w0.w * (g0.w / (1.f + expf(-g0.w)));
    f[4] = o1.x * r * w1.x * (g1.x / (1.f + expf(-g1.x)));
    f[5] = o1.y * r * w1.y * (g1.y / (1.f + expf(-g1.y)));
    f[6] = o1.z * r * w1.z * (g1.z / (1.f + expf(-g1.z)));
    f[7] = o1.w * r * w1.w * (g1.w / (1.f + expf(-g1.w)));
#pragma unroll
    for (int half = 0; half < 2; half++) {
        size_t base = (size_t)w * DVq + half * 128 + lane * 4;
        float a = f[half*4+0], b2 = f[half*4+1], c = f[half*4+2], d = f[half*4+3];
        split4h(make_float4(a, b2, c, d), oh + base, ol + base);
    }
}

// ------------------------- launch -------------------------------------------
extern "C" void kernel_launch(void* const* d_in, const int* in_sizes, int n_in,
                              void* d_out, int out_size)
{
    const float* h        = (const float*)d_in[0];
    const float* q_w      = (const float*)d_in[1];
    const float* k_w      = (const float*)d_in[2];
    const float* v_w      = (const float*)d_in[3];
    const float* a_w      = (const float*)d_in[4];
    const float* b_w      = (const float*)d_in[5];
    const float* g_w      = (const float*)d_in[6];
    const float* o_w      = (const float*)d_in[7];
    const float* q_conv_w = (const float*)d_in[8];
    const float* k_conv_w = (const float*)d_in[9];
    const float* v_conv_w = (const float*)d_in[10];
    const float* A_log    = (const float*)d_in[11];
    const float* dt_bias  = (const float*)d_in[12];
    const float* o_norm_w = (const float*)d_in[13];
    float* out = (float*)d_out;

    float *P, *qc, *kc, *vc, *gd, *bt, *orow;
    cudaGetSymbolAddress((void**)&P, g_proj);
    cudaGetSymbolAddress((void**)&qc, g_qc);
    cudaGetSymbolAddress((void**)&kc, g_kc);
    cudaGetSymbolAddress((void**)&vc, g_vc);
    cudaGetSymbolAddress((void**)&gd, g_gd);
    cudaGetSymbolAddress((void**)&bt, g_bt);
    cudaGetSymbolAddress((void**)&orow, g_orow);

    __half *hh, *hl, *wh, *owh, *onh, *onl;
    cudaGetSymbolAddress((void**)&hh, g_hh);   cudaGetSymbolAddress((void**)&hl, g_hl);
    cudaGetSymbolAddress((void**)&wh, g_wh);
    cudaGetSymbolAddress((void**)&owh, g_owh);
    cudaGetSymbolAddress((void**)&onh, g_onh); cudaGetSymbolAddress((void**)&onl, g_onl);

    cudaFuncSetAttribute(hgemm_nt_split, cudaFuncAttributeMaxDynamicSharedMemorySize, SMEM_GEMM);

    // 0) fp16 hi/lo splits (A sides) and hi-only (B sides)
    cvt_split<<<(Mrows*Dq/4 + 255)/256, 256>>>(h, hh, hl, Mrows*Dq);
    cvt_w4<<<(NFUSE*Dq/4 + 255)/256, 256>>>(q_w, k_w, v_w, g_w, wh);
    cvt_h<<<(Dq*VDq/4 + 255)/256, 256>>>(o_w, owh, Dq*VDq);

    // 1) fused q|k|v|gate projection on tensor cores (fp16 2-pass split)
    hgemm_nt_split<<<dim3(NFUSE/128, Mrows/128), 256, SMEM_GEMM>>>(hh, hl, wh, P, NFUSE);

    // 2) a/b projections -> decay + beta
    proj_ab_kernel<<<(Mrows * 32) / 256, 256>>>(h, a_w, b_w, A_log, dt_bias, gd, bt);

    // 3) conv+SiLU+l2norm for q,k ; conv+SiLU for v
    conv_l2_kernel<<<(Mrows * Hq * 32) / 256, 256>>>(P, 0,    q_conv_w, qc);
    conv_l2_kernel<<<(Mrows * Hq * 32) / 256, 256>>>(P, 1024, k_conv_w, kc);
    conv_silu_stride<<<(Mrows * VDq) / 256, 256>>>(P, 2048, v_conv_w, vc);

    // 4) gated delta-rule recurrence (16-col chunks, 256 CTAs, cp.async pipe)
    scan_kernel<<<dim3(DVq / 16, Hq, Bq), 128>>>(qc, kc, vc, gd, bt, orow);

    // 5) gated RMSNorm (+ fp16 hi/lo split)
    rmsnorm_gate_kernel<<<(Mrows * Hq * 32) / 256, 256>>>(orow, P, o_norm_w, onh, onl);

    // 6) output projection -> d_out
    hgemm_nt_split<<<dim3(Dq/128, Mrows/128), 256, SMEM_GEMM>>>(onh, onl, owh, out, Dq);
}

// round 15
// speedup vs baseline: 1.0057x; 1.0057x over previous
#include <cuda_runtime.h>
#include <cuda_bf16.h>
#include <cuda_fp16.h>
#include <math.h>
#include <stdint.h>

#define Bq 2
#define Tq 1024
#define Dq 2048
#define Hq 8
#define DKq 128
#define DVq 256
#define KDq 1024
#define VDq 2048
#define Mrows (Bq*Tq)   // 2048
#define GK 2048         // K for every big GEMM
#define NFUSE 6144      // q(1024) + k(1024) + v(2048) + gate(2048)

// ------------------------- scratch (device globals) -------------------------
__device__ float g_proj[Mrows*NFUSE];        // fused projection output
__device__ float g_qc[Mrows*KDq];
__device__ float g_kc[Mrows*KDq];
__device__ float g_vc[Mrows*VDq];
__device__ float g_gd[Mrows*Hq];
__device__ float g_bt[Mrows*Hq];
__device__ float g_orow[Mrows*VDq];

// fp16 split (hi/lo) operands; B side hi-only
__device__ __half g_hh[Mrows*Dq],    g_hl[Mrows*Dq];
__device__ __half g_wh[NFUSE*Dq];
__device__ __half g_owh[Dq*VDq];
__device__ __half g_onh[Mrows*VDq],  g_onl[Mrows*VDq];

// ------------------------- helpers ------------------------------------------
__device__ __forceinline__ uint32_t smem_u32(const void* p) {
    uint32_t a;
    asm("{ .reg .u64 t; cvta.to.shared.u64 t, %1; cvt.u32.u64 %0, t; }" : "=r"(a) : "l"(p));
    return a;
}
__device__ __forceinline__ void cp16(uint32_t dst, const void* src) {
    asm volatile("cp.async.cg.shared.global [%0], [%1], 16;" :: "r"(dst), "l"(src));
}
__device__ __forceinline__ void cp4(uint32_t dst, const void* src) {
    asm volatile("cp.async.ca.shared.global [%0], [%1], 4;" :: "r"(dst), "l"(src));
}
__device__ __forceinline__ void cp_commit() {
    asm volatile("cp.async.commit_group;" ::: "memory");
}
template <int N>
__device__ __forceinline__ void cp_wait() {
    asm volatile("cp.async.wait_group %0;" :: "n"(N) : "memory");
}
__device__ __forceinline__ void ldsm_x4(uint32_t addr, uint32_t* r) {
    asm volatile("ldmatrix.sync.aligned.m8n8.x4.shared.b16 {%0,%1,%2,%3}, [%4];"
                 : "=r"(r[0]), "=r"(r[1]), "=r"(r[2]), "=r"(r[3]) : "r"(addr));
}
__device__ __forceinline__ void mma_f16(float* c, const uint32_t* a, const uint32_t* b) {
    asm volatile(
        "mma.sync.aligned.m16n8k16.row.col.f32.f16.f16.f32 "
        "{%0,%1,%2,%3}, {%4,%5,%6,%7}, {%8,%9}, {%0,%1,%2,%3};"
        : "+f"(c[0]), "+f"(c[1]), "+f"(c[2]), "+f"(c[3])
        : "r"(a[0]), "r"(a[1]), "r"(a[2]), "r"(a[3]), "r"(b[0]), "r"(b[1]));
}

// ------------------------- split fp16 HMMA GEMM (3-stage, 2 CTA/SM) ---------
// C = A*B^T, A as fp16 hi/lo pair, B as fp16 hi only.
// A*B ~= Ah*Bh + Al*Bh (dropped A*Bl term ~2^-12 relative, within 1e-3 gate).
#define ROWB 80
#define MATB (128*ROWB)              // 10240 B per matrix
#define STGB (3*MATB)                // Ah,Al,Bh per stage = 30720 B
#define NSTG 3
#define SMEM_GEMM (NSTG*STGB)        // 92160 B (2 CTA/SM: 184320 <= 227KB)

__global__ void __launch_bounds__(256, 2) hgemm_nt_split(
    const __half* __restrict__ Ah, const __half* __restrict__ Al,
    const __half* __restrict__ Bh,
    float* __restrict__ C, int N)
{
    extern __shared__ char smem[];
    const uint32_t sb = smem_u32(smem);
    const int tid = threadIdx.x, wid = tid >> 5, lane = tid & 31;
    const int bm = blockIdx.y * 128, bn = blockIdx.x * 128;
    const int wm = (wid >> 1) * 32;
    const int wn = (wid & 1) * 64;

    float acc[2][8][4];
#pragma unroll
    for (int i = 0; i < 2; i++)
#pragma unroll
        for (int j = 0; j < 8; j++)
#pragma unroll
            for (int l = 0; l < 4; l++) acc[i][j][l] = 0.f;

    const int NC = GK / 32;   // 64

#define PREFETCH(cc)                                                              \
    {                                                                             \
        const int kc = (cc) * 32;                                                 \
        const uint32_t stg = sb + (uint32_t)((cc) % NSTG) * STGB;                 \
        _Pragma("unroll")                                                         \
        for (int i = 0; i < 2; i++) {                                             \
            int idx = tid + i * 256;                                              \
            int row = idx >> 2, seg = idx & 3;                                    \
            uint32_t so = (uint32_t)(row * ROWB + seg * 16);                      \
            size_t ea = (size_t)(bm + row) * GK + kc + seg * 8;                   \
            size_t eb = (size_t)(bn + row) * GK + kc + seg * 8;                   \
            cp16(stg + so,            Ah + ea);                                   \
            cp16(stg + MATB + so,     Al + ea);                                   \
            cp16(stg + 2*MATB + so,   Bh + eb);                                   \
        }                                                                         \
        cp_commit();                                                              \
    }

    PREFETCH(0); PREFETCH(1); PREFETCH(2);

    const uint32_t a_row = (uint32_t)(wm + (lane & 15));
    const uint32_t a_colb = (uint32_t)((lane >> 4) * 16);
    const uint32_t b_row0 = (uint32_t)(wn + (lane & 7) + ((lane >> 4) << 3));
    const uint32_t b_colb = (uint32_t)(((lane >> 3) & 1) * 16);

    for (int c = 0; c < NC; c++) {
        if (c < NC - 2) cp_wait<2>();
        else if (c == NC - 2) cp_wait<1>();
        else cp_wait<0>();
        __syncthreads();
        const uint32_t stg = sb + (uint32_t)(c % NSTG) * STGB;

#pragma unroll
        for (int k16 = 0; k16 < 2; k16++) {
            const uint32_t kb = (uint32_t)(k16 * 32);
            uint32_t a0[2][4], a1[2][4], bb[4][4];

            // pass 1: Ah*Bh (16 distinct accs)
#pragma unroll
            for (int mt = 0; mt < 2; mt++) {
                uint32_t ao = (a_row + mt * 16) * ROWB + kb + a_colb;
                ldsm_x4(stg + ao, a0[mt]);
            }
#pragma unroll
            for (int np = 0; np < 4; np++) {
                uint32_t bo = (b_row0 + np * 16) * ROWB + kb + b_colb;
                ldsm_x4(stg + 2*MATB + bo, bb[np]);
            }
#pragma unroll
            for (int mt = 0; mt < 2; mt++)
#pragma unroll
                for (int np = 0; np < 4; np++) {
                    mma_f16(acc[mt][np*2],   a0[mt], bb[np]);
                    mma_f16(acc[mt][np*2+1], a0[mt], bb[np] + 2);
                }

            // pass 2: Al*Bh (16 distinct accs)
#pragma unroll
            for (int mt = 0; mt < 2; mt++) {
                uint32_t ao = (a_row + mt * 16) * ROWB + kb + a_colb;
                ldsm_x4(stg + MATB + ao, a1[mt]);
            }
#pragma unroll
            for (int mt = 0; mt < 2; mt++)
#pragma unroll
                for (int np = 0; np < 4; np++) {
                    mma_f16(acc[mt][np*2],   a1[mt], bb[np]);
                    mma_f16(acc[mt][np*2+1], a1[mt], bb[np] + 2);
                }
        }
        __syncthreads();
        if (c + NSTG < NC) PREFETCH(c + NSTG);
    }
#undef PREFETCH

#pragma unroll
    for (int mt = 0; mt < 2; mt++) {
        int r0 = bm + wm + mt * 16 + (lane >> 2);
#pragma unroll
        for (int nt = 0; nt < 8; nt++) {
            int col = bn + wn + nt * 8 + (lane & 3) * 2;
            float2 v0 = make_float2(acc[mt][nt][0], acc[mt][nt][1]);
            float2 v1 = make_float2(acc[mt][nt][2], acc[mt][nt][3]);
            *(float2*)(C + (size_t)r0 * N + col)       = v0;
            *(float2*)(C + (size_t)(r0 + 8) * N + col) = v1;
        }
    }
}

// ------------------------- fp32 -> fp16 hi/lo split -------------------------
__device__ __forceinline__ void split4h(float4 v, __half* hi, __half* lo) {
    __half hx = __float2half(v.x), hy = __float2half(v.y);
    __half hz = __float2half(v.z), hw = __float2half(v.w);
    __half2 h0, h1, l0, l1;
    h0.x = hx; h0.y = hy; h1.x = hz; h1.y = hw;
    l0.x = __float2half(v.x - __half2float(hx));
    l0.y = __float2half(v.y - __half2float(hy));
    l1.x = __float2half(v.z - __half2float(hz));
    l1.y = __float2half(v.w - __half2float(hw));
    *(__half2*)(hi)     = h0;
    *(__half2*)(hi + 2) = h1;
    *(__half2*)(lo)     = l0;
    *(__half2*)(lo + 2) = l1;
}
__device__ __forceinline__ void cvt4h(float4 v, __half* hi) {
    __half2 h0, h1;
    h0.x = __float2half(v.x); h0.y = __float2half(v.y);
    h1.x = __float2half(v.z); h1.y = __float2half(v.w);
    *(__half2*)(hi)     = h0;
    *(__half2*)(hi + 2) = h1;
}

__global__ void cvt_split(const float* __restrict__ x,
                          __half* __restrict__ hi,
                          __half* __restrict__ lo, int n)
{
    int i = (blockIdx.x * blockDim.x + threadIdx.x) * 4;
    if (i >= n) return;
    split4h(*(const float4*)(x + i), hi + i, lo + i);
}

// fused weight convert (hi only): rows 0-1023 q_w, 1024-2047 k_w, 2048-4095 v_w, 4096-6143 g_w
__global__ void cvt_w4(const float* __restrict__ qw, const float* __restrict__ kw,
                       const float* __restrict__ vw, const float* __restrict__ gw,
                       __half* __restrict__ hi)
{
    int i = (blockIdx.x * blockDim.x + threadIdx.x) * 4;
    int row = i >> 11;
    int col = i & 2047;
    const float* src;
    if (row < 1024)      src = qw + (size_t)row * Dq + col;
    else if (row < 2048) src = kw + (size_t)(row - 1024) * Dq + col;
    else if (row < 4096) src = vw + (size_t)(row - 2048) * Dq + col;
    else                 src = gw + (size_t)(row - 4096) * Dq + col;
    cvt4h(*(const float4*)src, hi + i);
}

__global__ void cvt_h(const float* __restrict__ x, __half* __restrict__ hi, int n)
{
    int i = (blockIdx.x * blockDim.x + threadIdx.x) * 4;
    if (i >= n) return;
    cvt4h(*(const float4*)(x + i), hi + i);
}

// ------------------------- a/b projections -> decay g and beta --------------
__device__ __forceinline__ float softplus_f(float x) {
    return fmaxf(x, 0.f) + log1pf(expf(-fabsf(x)));
}

__global__ void proj_ab_kernel(const float* __restrict__ h,
                               const float* __restrict__ a_w,
                               const float* __restrict__ b_w,
                               const float* __restrict__ A_log,
                               const float* __restrict__ dt_bias,
                               float* __restrict__ gd, float* __restrict__ bt)
{
    int w = (blockIdx.x * blockDim.x + threadIdx.x) >> 5;
    int lane = threadIdx.x & 31;
    if (w >= Mrows) return;
    const float* hr = h + (size_t)w * Dq;
    float acc[16];
#pragma unroll
    for (int p = 0; p < 16; p++) acc[p] = 0.f;
    for (int j = lane * 4; j < Dq; j += 128) {
        float4 hv = *(const float4*)(hr + j);
#pragma unroll
        for (int p = 0; p < 8; p++) {
            float4 av = *(const float4*)(a_w + (size_t)p * Dq + j);
            acc[p] += hv.x * av.x + hv.y * av.y + hv.z * av.z + hv.w * av.w;
            float4 bv = *(const float4*)(b_w + (size_t)p * Dq + j);
            acc[8 + p] += hv.x * bv.x + hv.y * bv.y + hv.z * bv.z + hv.w * bv.w;
        }
    }
#pragma unroll
    for (int p = 0; p < 16; p++)
#pragma unroll
        for (int m = 16; m; m >>= 1)
            acc[p] += __shfl_xor_sync(0xffffffffu, acc[p], m);

    if (lane < 8) {
        float x = acc[lane] + dt_bias[lane];
        gd[w * Hq + lane] = -expf(A_log[lane]) * softplus_f(x);
    } else if (lane < 16) {
        int p = lane - 8;
        bt[w * Hq + p] = 1.f / (1.f + expf(-acc[lane]));
    }
}

// ---------------- fused conv+SiLU+l2norm for q/k (head dim 128) -------------
__global__ void conv_l2_kernel(const float* __restrict__ P, int colofs,
                               const float* __restrict__ w, float* __restrict__ out)
{
    int gwp = (blockIdx.x * blockDim.x + threadIdx.x) >> 5;
    int lane = threadIdx.x & 31;
    int row = gwp >> 3, hh = gwp & 7;
    int t = row & (Tq - 1);
    int c = hh * 128 + lane * 4;
    const float* base = P + (size_t)row * NFUSE + colofs + c;
    float4 x0 = *(const float4*)base;
    float4 x1 = make_float4(0,0,0,0), x2 = x1, x3 = x1;
    if (t >= 1) x1 = *(const float4*)(base - NFUSE);
    if (t >= 2) x2 = *(const float4*)(base - 2*NFUSE);
    if (t >= 3) x3 = *(const float4*)(base - 3*NFUSE);
    float4 wc0 = *(const float4*)(w + (size_t)(c + 0) * 4);
    float4 wc1 = *(const float4*)(w + (size_t)(c + 1) * 4);
    float4 wc2 = *(const float4*)(w + (size_t)(c + 2) * 4);
    float4 wc3 = *(const float4*)(w + (size_t)(c + 3) * 4);
    float v0 = x0.x*wc0.w + x1.x*wc0.z + x2.x*wc0.y + x3.x*wc0.x;
    float v1 = x0.y*wc1.w + x1.y*wc1.z + x2.y*wc1.y + x3.y*wc1.x;
    float v2 = x0.z*wc2.w + x1.z*wc2.z + x2.z*wc2.y + x3.z*wc2.x;
    float v3 = x0.w*wc3.w + x1.w*wc3.z + x2.w*wc3.y + x3.w*wc3.x;
    v0 = v0 / (1.f + expf(-v0));
    v1 = v1 / (1.f + expf(-v1));
    v2 = v2 / (1.f + expf(-v2));
    v3 = v3 / (1.f + expf(-v3));
    float ss = v0*v0 + v1*v1 + v2*v2 + v3*v3;
#pragma unroll
    for (int m = 16; m; m >>= 1) ss += __shfl_xor_sync(0xffffffffu, ss, m);
    float r = rsqrtf(ss + 1e-6f);
    *(float4*)(out + (size_t)row * KDq + c) =
        make_float4(v0 * r, v1 * r, v2 * r, v3 * r);
}

// ---------------- conv+SiLU for v (elementwise, strided read) ---------------
__global__ void conv_silu_stride(const float* __restrict__ P, int colofs,
                                 const float* __restrict__ w, float* __restrict__ out)
{
    int i = blockIdx.x * blockDim.x + threadIdx.x;
    int c = i % VDq;
    int row = i / VDq;
    int t = row & (Tq - 1);
    const float* base = P + (size_t)row * NFUSE + colofs + c;
    float4 wc = *(const float4*)(w + (size_t)c * 4);
    float acc = base[0] * wc.w;
    if (t >= 1) acc += base[-1 * NFUSE] * wc.z;
    if (t >= 2) acc += base[-2 * NFUSE] * wc.y;
    if (t >= 3) acc += base[-3 * NFUSE] * wc.x;
    out[i] = acc / (1.f + expf(-acc));
}

// ------------------------- gated delta-rule scan (16-col chunks) ------------
#define TS 16
#define GSTR 160
#define QOFF (TS*GSTR)
#define VOFF (2*TS*GSTR)
#define GOFF (VOFF + TS*16)
#define SSZ  (GOFF + 32)

__global__ void __launch_bounds__(128) scan_kernel(const float* __restrict__ q,
                                                   const float* __restrict__ k,
                                                   const float* __restrict__ v,
                                                   const float* __restrict__ gdec,
                                                   const float* __restrict__ beta,
                                                   float* __restrict__ o)
{
    const int vchunk = blockIdx.x;
    const int h = blockIdx.y;
    const int b = blockIdx.z;
    const int tid = threadIdx.x;
    const int col = tid >> 3;
    const int rgrp = tid & 7;
    const int c0 = vchunk * 16;

    __shared__ float sbuf[2 * SSZ];
    const uint32_t sb = smem_u32(sbuf);

    float S[16];
#pragma unroll
    for (int i = 0; i < 16; i++) S[i] = 0.f;
    const float scale = 0.08838834764831843f;
    const int NT = Tq / TS;

#define SPRE(tt, ss)                                                              \
    {                                                                             \
        const int tb = (tt) * TS;                                                 \
        const uint32_t stb = sb + (uint32_t)(ss) * (SSZ * 4);                     \
        _Pragma("unroll")                                                         \
        for (int j = 0; j < 4; j++) {                                             \
            int idx = tid + j * 128;                                              \
            int s = idx >> 5, f = idx & 31;                                       \
            size_t gofs = ((size_t)(b * Tq + tb + s)) * KDq + h * DKq + f * 4;    \
            uint32_t so = (uint32_t)((s * GSTR + (f >> 2) * 20 + (f & 3) * 4)*4); \
            cp16(stb + so, k + gofs);                                             \
            cp16(stb + QOFF * 4 + so, q + gofs);                                  \
        }                                                                         \
        if (tid < 64) {                                                           \
            int s = tid >> 2, f = tid & 3;                                        \
            size_t gofs = ((size_t)(b * Tq + tb + s)) * VDq + h * DVq + c0 + f*4; \
            cp16(stb + (VOFF + s * 16 + f * 4) * 4, v + gofs);                    \
        } else if (tid < 80) {                                                    \
            int s = tid - 64;                                                     \
            cp4(stb + (GOFF + s) * 4, gdec + (size_t)(b * Tq + tb + s) * Hq + h); \
        } else if (tid < 96) {                                                    \
            int s = tid - 80;                                                     \
            cp4(stb + (GOFF + 16 + s) * 4, beta + (size_t)(b * Tq + tb + s) * Hq + h); \
        }                                                                         \
        cp_commit();                                                              \
    }

    SPRE(0, 0);
    SPRE(1, 1);

    for (int t = 0; t < NT; t++) {
        if (t == NT - 1) cp_wait<0>(); else cp_wait<1>();
        __syncthreads();
        const float* st = sbuf + (t & 1) * SSZ;
        const float* ksb = st;
        const float* qsb = st + QOFF;
        const float* vsb = st + VOFF;
        const float* gsb = st + GOFF;
        const int trow = b * Tq + t * TS;

#pragma unroll
        for (int s = 0; s < TS; s++) {
            const float* kb = ksb + s * GSTR + rgrp * 20;
            const float* qb = qsb + s * GSTR + rgrp * 20;
            float4 k0 = *(const float4*)(kb);
            float4 k1 = *(const float4*)(kb + 4);
            float4 k2 = *(const float4*)(kb + 8);
            float4 k3 = *(const float4*)(kb + 12);
            float kva = k0.x*S[0] + k0.y*S[1] + k0.z*S[2] + k0.w*S[3];
            float kvb = k1.x*S[4] + k1.y*S[5] + k1.z*S[6] + k1.w*S[7];
            float kvc = k2.x*S[8] + k2.y*S[9] + k2.z*S[10] + k2.w*S[11];
            float kvd = k3.x*S[12] + k3.y*S[13] + k3.z*S[14] + k3.w*S[15];
            float kv = (kva + kvb) + (kvc + kvd);
            kv += __shfl_xor_sync(0xffffffffu, kv, 1);
            kv += __shfl_xor_sync(0xffffffffu, kv, 2);
            kv += __shfl_xor_sync(0xffffffffu, kv, 4);
            float eg = expf(gsb[s]);
            float u = (vsb[s * 16 + col] - kv * eg) * gsb[16 + s];
            float4 q0 = *(const float4*)(qb);
            float4 q1 = *(const float4*)(qb + 4);
            float4 q2 = *(const float4*)(qb + 8);
            float4 q3 = *(const float4*)(qb + 12);
            S[0]  = S[0]*eg  + k0.x*u;  S[1]  = S[1]*eg  + k0.y*u;
            S[2]  = S[2]*eg  + k0.z*u;  S[3]  = S[3]*eg  + k0.w*u;
            S[4]  = S[4]*eg  + k1.x*u;  S[5]  = S[5]*eg  + k1.y*u;
            S[6]  = S[6]*eg  + k1.z*u;  S[7]  = S[7]*eg  + k1.w*u;
            S[8]  = S[8]*eg  + k2.x*u;  S[9]  = S[9]*eg  + k2.y*u;
            S[10] = S[10]*eg + k2.z*u;  S[11] = S[11]*eg + k2.w*u;
            S[12] = S[12]*eg + k3.x*u;  S[13] = S[13]*eg + k3.y*u;
            S[14] = S[14]*eg + k3.z*u;  S[15] = S[15]*eg + k3.w*u;
            float oa = q0.x*S[0] + q0.y*S[1] + q0.z*S[2] + q0.w*S[3];
            float ob = q1.x*S[4] + q1.y*S[5] + q1.z*S[6] + q1.w*S[7];
            float oc = q2.x*S[8] + q2.y*S[9] + q2.z*S[10] + q2.w*S[11];
            float od = q3.x*S[12] + q3.y*S[13] + q3.z*S[14] + q3.w*S[15];
            float ot = (oa + ob) + (oc + od);
            ot += __shfl_xor_sync(0xffffffffu, ot, 1);
            ot += __shfl_xor_sync(0xffffffffu, ot, 2);
            ot += __shfl_xor_sync(0xffffffffu, ot, 4);
            if (rgrp == 0)
                o[(size_t)(trow + s) * VDq + h * DVq + c0 + col] = ot * scale;
        }
        __syncthreads();
        if (t + 2 < NT) SPRE(t + 2, t & 1);
    }
#undef SPRE
}

// ------------------------- gated RMSNorm -> fp16 hi/lo ----------------------
__global__ void rmsnorm_gate_kernel(const float* __restrict__ o,
                                    const float* __restrict__ P,   // gate at col 4096
                                    const float* __restrict__ nw,
                                    __half* __restrict__ oh,
                                    __half* __restrict__ ol)
{
    int w = (blockIdx.x * blockDim.x + threadIdx.x) >> 5;
    int lane = threadIdx.x & 31;
    int row = w >> 3, hh = w & 7;
    const float* orow = o + (size_t)w * DVq;
    float4 o0 = *(const float4*)(orow + lane * 4);
    float4 o1 = *(const float4*)(orow + 128 + lane * 4);
    float ss = o0.x * o0.x + o0.y * o0.y + o0.z * o0.z + o0.w * o0.w
             + o1.x * o1.x + o1.y * o1.y + o1.z * o1.z + o1.w * o1.w;
#pragma unroll
    for (int m = 16; m; m >>= 1) ss += __shfl_xor_sync(0xffffffffu, ss, m);
    float r = rsqrtf(ss * (1.f / 256.f) + 1e-5f);
    const float* grow = P + (size_t)row * NFUSE + 4096 + hh * DVq;
    float4 g0 = *(const float4*)(grow + lane * 4);
    float4 g1 = *(const float4*)(grow + 128 + lane * 4);
    float4 w0 = *(const float4*)(nw + lane * 4);
    float4 w1 = *(const float4*)(nw + 128 + lane * 4);
    float f[8];
    f[0] = o0.x * r * w0.x * (g0.x / (1.f + expf(-g0.x)));
    f[1] = o0.y * r * w0.y * (g0.y / (1.f + expf(-g0.y)));
    f[2] = o0.z * r * w0.z * (g0.z / (1.f + expf(-g0.z)));
    f[3] = o0.w * r * w0.w * (g0.w / (1.f + expf(-g0.w)));
    f[4] = o1.x * r * w1.x * (g1.x / (1.f + expf(-g1.x)));
    f[5] = o1.y * r * w1.y * (g1.y / (1.f + expf(-g1.y)));
    f[6] = o1.z * r * w1.z * (g1.z / (1.f + expf(-g1.z)));
    f[7] = o1.w * r * w1.w * (g1.w / (1.f + expf(-g1.w)));
#pragma unroll
    for (int half = 0; half < 2; half++) {
        size_t base = (size_t)w * DVq + half * 128 + lane * 4;
        float a = f[half*4+0], b2 = f[half*4+1], c = f[half*4+2], d = f[half*4+3];
        split4h(make_float4(a, b2, c, d), oh + base, ol + base);
    }
}

// ------------------------- launch -------------------------------------------
extern "C" void kernel_launch(void* const* d_in, const int* in_sizes, int n_in,
                              void* d_out, int out_size)
{
    const float* h        = (const float*)d_in[0];
    const float* q_w      = (const float*)d_in[1];
    const float* k_w      = (const float*)d_in[2];
    const float* v_w      = (const float*)d_in[3];
    const float* a_w      = (const float*)d_in[4];
    const float* b_w      = (const float*)d_in[5];
    const float* g_w      = (const float*)d_in[6];
    const float* o_w      = (const float*)d_in[7];
    const float* q_conv_w = (const float*)d_in[8];
    const float* k_conv_w = (const float*)d_in[9];
    const float* v_conv_w = (const float*)d_in[10];
    const float* A_log    = (const float*)d_in[11];
    const float* dt_bias  = (const float*)d_in[12];
    const float* o_norm_w = (const float*)d_in[13];
    float* out = (float*)d_out;

    float *P, *qc, *kc, *vc, *gd, *bt, *orow;
    cudaGetSymbolAddress((void**)&P, g_proj);
    cudaGetSymbolAddress((void**)&qc, g_qc);
    cudaGetSymbolAddress((void**)&kc, g_kc);
    cudaGetSymbolAddress((void**)&vc, g_vc);
    cudaGetSymbolAddress((void**)&gd, g_gd);
    cudaGetSymbolAddress((void**)&bt, g_bt);
    cudaGetSymbolAddress((void**)&orow, g_orow);

    __half *hh, *hl, *wh, *owh, *onh, *onl;
    cudaGetSymbolAddress((void**)&hh, g_hh);   cudaGetSymbolAddress((void**)&hl, g_hl);
    cudaGetSymbolAddress((void**)&wh, g_wh);
    cudaGetSymbolAddress((void**)&owh, g_owh);
    cudaGetSymbolAddress((void**)&onh, g_onh); cudaGetSymbolAddress((void**)&onl, g_onl);

    cudaFuncSetAttribute(hgemm_nt_split, cudaFuncAttributeMaxDynamicSharedMemorySize, SMEM_GEMM);

    // 0) fp16 hi/lo splits (A sides) and hi-only (B sides)
    cvt_split<<<(Mrows*Dq/4 + 255)/256, 256>>>(h, hh, hl, Mrows*Dq);
    cvt_w4<<<(NFUSE*Dq/4 + 255)/256, 256>>>(q_w, k_w, v_w, g_w, wh);
    cvt_h<<<(Dq*VDq/4 + 255)/256, 256>>>(o_w, owh, Dq*VDq);

    // 1) fused q|k|v|gate projection on tensor cores (fp16 2-pass, 3-stage)
    hgemm_nt_split<<<dim3(NFUSE/128, Mrows/128), 256, SMEM_GEMM>>>(hh, hl, wh, P, NFUSE);

    // 2) a/b projections -> decay + beta
    proj_ab_kernel<<<(Mrows * 32) / 256, 256>>>(h, a_w, b_w, A_log, dt_bias, gd, bt);

    // 3) conv+SiLU+l2norm for q,k ; conv+SiLU for v
    conv_l2_kernel<<<(Mrows * Hq * 32) / 256, 256>>>(P, 0,    q_conv_w, qc);
    conv_l2_kernel<<<(Mrows * Hq * 32) / 256, 256>>>(P, 1024, k_conv_w, kc);
    conv_silu_stride<<<(Mrows * VDq) / 256, 256>>>(P, 2048, v_conv_w, vc);

    // 4) gated delta-rule recurrence (16-col chunks, 256 CTAs, cp.async pipe)
    scan_kernel<<<dim3(DVq / 16, Hq, Bq), 128>>>(qc, kc, vc, gd, bt, orow);

    // 5) gated RMSNorm (+ fp16 hi/lo split)
    rmsnorm_gate_kernel<<<(Mrows * Hq * 32) / 256, 256>>>(orow, P, o_norm_w, onh, onl);

    // 6) output projection -> d_out
    hgemm_nt_split<<<dim3(Dq/128, Mrows/128), 256, SMEM_GEMM>>>(onh, onl, owh, out, Dq);
}